// round 16
// baseline (speedup 1.0000x reference)
#include <cuda_runtime.h>
#include <cuda_fp16.h>
#include <stdint.h>

#define N_TOK 32768
#define EMB_D 1024
#define BM 128
#define BN 128
#define BKH 64          // k-tile in halves (128 bytes)

#define A_TILE_B (BM * BKH * 2)       // 16KB
#define B_TILE_B (BKH * BN * 2)       // 16KB
#define SMEM_BYTES (2 * A_TILE_B + 2 * B_TILE_B + BM * 4)
#define MAX_TILES 264

// device scratch (no runtime allocation allowed)
__device__ int g_counts[4];
__device__ int g_list[4 * N_TOK];
__device__ int g_rows[4 * N_TOK];
__device__ int g_ntiles;
__device__ int g_tile_b[MAX_TILES];
__device__ int g_tile_m[MAX_TILES];
__device__ __half g_Wh[1966080];            // all W tables, fp16, K-major
__device__ __half g_Ah[62914560];           // packed gathered A rows, fp16

__constant__ long long c_abase[4] = {0, 33554432, 50331648, 58720256};
__constant__ long long c_wbase[4] = {0, 1048576, 1572864, 1835008};
__constant__ int c_d[4] = {1024, 512, 256, 128};

struct Params {
    const float* emb[4];
    const float* W[4];
    int d[4];
};

__device__ __forceinline__ uint32_t pack_h2(float a, float b) {
    __half2 h = __floats2half2_rn(a, b);
    return *(uint32_t*)&h;
}

__device__ __forceinline__ void cp16(uint32_t sdst, const __half* gsrc, bool full) {
    int sz = full ? 16 : 0;
    asm volatile("cp.async.cg.shared.global [%0], [%1], 16, %2;\n"
                 :: "r"(sdst), "l"(gsrc), "r"(sz));
}

__device__ __forceinline__ void ldsm_x4(uint32_t* r, uint32_t addr) {
    asm volatile("ldmatrix.sync.aligned.m8n8.x4.shared.b16 {%0,%1,%2,%3}, [%4];"
                 : "=r"(r[0]), "=r"(r[1]), "=r"(r[2]), "=r"(r[3]) : "r"(addr));
}
__device__ __forceinline__ void ldsm_x4_t(uint32_t* r, uint32_t addr) {
    asm volatile("ldmatrix.sync.aligned.m8n8.x4.trans.shared.b16 {%0,%1,%2,%3}, [%4];"
                 : "=r"(r[0]), "=r"(r[1]), "=r"(r[2]), "=r"(r[3]) : "r"(addr));
}

// ---------------- stage 1: classify (blocks 0-127) + W convert (blocks 128-639) ----------------

__global__ void classify_wconv_kernel(const void* __restrict__ xraw, Params p) {
    const int blk = blockIdx.x;
    const int tid = threadIdx.x;

    if (blk >= 128) {
        // W conversion, independent of classify: 245,760 8-float chunks / 512 blocks
        const int t0 = (blk - 128) * 256 + tid;
        for (int idx = t0; idx < 1966080 / 8; idx += 512 * 256) {
            long long i = (long long)idx * 8;
            int b = (i >= c_wbase[3]) ? 3 : (i >= c_wbase[2]) ? 2 :
                    (i >= c_wbase[1]) ? 1 : 0;
            const float* src = p.W[b] + (i - c_wbase[b]);
            float4 v0 = *(const float4*)(src);
            float4 v1 = *(const float4*)(src + 4);
            uint4 u = make_uint4(pack_h2(v0.x, v0.y), pack_h2(v0.z, v0.w),
                                 pack_h2(v1.x, v1.y), pack_h2(v1.z, v1.w));
            *(uint4*)&g_Wh[i] = u;
        }
        return;
    }

    __shared__ int s_cnt[4];
    __shared__ int s_base[4];
    __shared__ int s_warp[8][4];
    const int lane = tid & 31;
    const int wid = tid >> 5;
    const int i = blk * 256 + tid;
    if (tid < 4) s_cnt[tid] = 0;
    __syncthreads();

    // dtype-robust id load (JAX default x64-off => int32)
    const unsigned int* xw = (const unsigned int*)xraw;
    unsigned int probe = xw[2 * (tid & 15) + 1];
    bool is64 = __all_sync(0xFFFFFFFFu, probe == 0u);

    int v;
    if (is64) v = (int)((const long long*)xraw)[i];
    else      v = ((const int*)xraw)[i];

    int b, lo;
    if (v >= 30000)     { b = 3; lo = 30000; }
    else if (v >= 3000) { b = 2; lo = 3000; }
    else if (v >= 300)  { b = 1; lo = 300; }
    else                { b = 0; lo = 0; }

    const uint32_t m0 = __ballot_sync(0xFFFFFFFFu, b == 0);
    const uint32_t m1 = __ballot_sync(0xFFFFFFFFu, b == 1);
    const uint32_t m2 = __ballot_sync(0xFFFFFFFFu, b == 2);
    const uint32_t m3 = __ballot_sync(0xFFFFFFFFu, b == 3);
    const uint32_t mb = (b == 0) ? m0 : (b == 1) ? m1 : (b == 2) ? m2 : m3;
    const int rank = __popc(mb & ((1u << lane) - 1));

    if (lane < 4) {
        uint32_t mk = (lane == 0) ? m0 : (lane == 1) ? m1 : (lane == 2) ? m2 : m3;
        s_warp[wid][lane] = atomicAdd(&s_cnt[lane], __popc(mk));
    }
    __syncthreads();
    if (tid < 4) s_base[tid] = atomicAdd(&g_counts[tid], s_cnt[tid]);
    __syncthreads();

    const int pos = s_base[b] + s_warp[wid][b] + rank;
    g_list[b * N_TOK + pos] = i;
    g_rows[b * N_TOK + pos] = v - lo;
}

// ---------------- stage 2: gather A rows (+ tile table) ----------------

__global__ void gather_kernel(Params p) {
    const int b = blockIdx.y;
    const int t0 = blockIdx.x * 256 + threadIdx.x;
    const int stride = gridDim.x * 256;

    if (b == 0 && blockIdx.x == 0 && threadIdx.x == 0) {
        int n = 0;
        for (int bb = 0; bb < 4; bb++) {
            int nt = (g_counts[bb] + BM - 1) / BM;
            for (int m = 0; m < nt; m++) {
                g_tile_b[n] = bb;
                g_tile_m[n] = m;
                n++;
            }
        }
        g_ntiles = n;
    }

    const int d = p.d[b];
    const int lg = (d == 1024) ? 7 : (d == 512) ? 6 : (d == 256) ? 5 : 4;
    const int cmask = (1 << lg) - 1;
    const int total = g_counts[b] << lg;
    const float* __restrict__ emb = p.emb[b];
    __half* __restrict__ dst0 = g_Ah + c_abase[b];
    const int* __restrict__ rows = g_rows + b * N_TOK;

    for (int idx = t0; idx < total; idx += stride) {
        int e = idx >> lg;
        int c = (idx & cmask) * 8;
        const float* src = emb + (long long)rows[e] * d + c;
        float4 v0 = *(const float4*)(src);
        float4 v1 = *(const float4*)(src + 4);
        uint4 u = make_uint4(pack_h2(v0.x, v0.y), pack_h2(v0.z, v0.w),
                             pack_h2(v1.x, v1.y), pack_h2(v1.z, v1.w));
        *(uint4*)&dst0[(long long)e * d + c] = u;
    }
}

// ---------------- GEMM (R15 verbatim) ----------------

__global__ __launch_bounds__(256, 2)
void bucket_gemm_f16_kernel(float* __restrict__ out) {
    const int ty = blockIdx.y;
    if (ty >= g_ntiles) return;
    const int b = g_tile_b[ty];
    const int count = g_counts[b];
    const int row0 = g_tile_m[ty] * BM;

    const int d = c_d[b];
    const int col0 = blockIdx.x * BN;
    const __half* __restrict__ Ab = g_Ah + c_abase[b];
    const __half* __restrict__ Wb = g_Wh + c_wbase[b];

    extern __shared__ __align__(16) char smem[];
    char* A_sm = smem;
    char* B_sm = smem + 2 * A_TILE_B;
    int* s_tok = (int*)(smem + 2 * A_TILE_B + 2 * B_TILE_B);

    const uint32_t sA = (uint32_t)__cvta_generic_to_shared(A_sm);
    const uint32_t sB = (uint32_t)__cvta_generic_to_shared(B_sm);

    const int tid = threadIdx.x;
    const int lane = tid & 31;
    const int wid = tid >> 5;
    const int g = lane >> 2;
    const int tig = lane & 3;
    const int warp_m = (wid & 3) * 32;
    const int warp_n = (wid >> 2) * 64;

    if (tid < BM) {
        s_tok[tid] = (row0 + tid < count) ? g_list[b * N_TOK + row0 + tid] : 0;
    }

    const int a_r = tid >> 1;
    const int a_c0 = (tid & 1) * 4;
    const bool a_ok = (row0 + a_r) < count;
    const __half* a_src = Ab + (long long)(row0 + a_r) * d;
    const int b_r = tid >> 2;
    const int b_c0 = (tid & 3) * 4;
    const __half* b_src = Wb + (long long)b_r * EMB_D + col0;

    auto stage = [&](int it, int buf) {
        uint32_t adst = sA + buf * A_TILE_B + a_r * 128;
        const __half* as = a_src + it * BKH;
#pragma unroll
        for (int j = 0; j < 4; j++) {
            int c = a_c0 + j;
            cp16(adst + ((c ^ (a_r & 7)) << 4), as + c * 8, a_ok);
        }
        uint32_t bdst = sB + buf * B_TILE_B + b_r * 256;
        const __half* bs = b_src + (long long)(it * BKH) * EMB_D;
#pragma unroll
        for (int j = 0; j < 4; j++) {
            int c = b_c0 + j;
            int cs = (c & 8) | ((c & 7) ^ (b_r & 7));
            cp16(bdst + (cs << 4), bs + c * 8, true);
        }
        asm volatile("cp.async.commit_group;\n" ::: "memory");
    };

    float acc[2][8][4];
#pragma unroll
    for (int mt = 0; mt < 2; mt++)
#pragma unroll
        for (int nt = 0; nt < 8; nt++)
#pragma unroll
            for (int c = 0; c < 4; c++) acc[mt][nt][c] = 0.0f;

    const int T = d / BKH;   // 16/8/4/2
    stage(0, 0);
    if (T > 1) stage(1, 1);

    for (int it = 0; it < T; it++) {
        const int cur = it & 1;
        if (it + 1 < T)
            asm volatile("cp.async.wait_group 1;\n" ::: "memory");
        else
            asm volatile("cp.async.wait_group 0;\n" ::: "memory");
        __syncthreads();

        const uint32_t aBase = sA + cur * A_TILE_B;
        const uint32_t bBase = sB + cur * B_TILE_B;
#pragma unroll
        for (int ks = 0; ks < 4; ks++) {
            const int kk = ks * 16;
            uint32_t a[2][4];
#pragma unroll
            for (int mt = 0; mt < 2; mt++) {
                int r = warp_m + mt * 16 + (lane & 15);
                int chunk = (kk >> 3) + (lane >> 4);
                ldsm_x4(a[mt], aBase + r * 128 + ((chunk ^ (r & 7)) << 4));
            }
            uint32_t bf[4][4];
#pragma unroll
            for (int pr = 0; pr < 4; pr++) {
                int kr = kk + (lane & 15);
                int chunk = (warp_n >> 3) + pr * 2 + (lane >> 4);
                int cs = (chunk & 8) | ((chunk & 7) ^ (kr & 7));
                ldsm_x4_t(bf[pr], bBase + kr * 256 + (cs << 4));
            }
#pragma unroll
            for (int mt = 0; mt < 2; mt++)
#pragma unroll
                for (int nt = 0; nt < 8; nt++) {
                    const uint32_t* bb = &bf[nt >> 1][(nt & 1) * 2];
                    asm volatile(
                        "mma.sync.aligned.m16n8k16.row.col.f32.f16.f16.f32 "
                        "{%0,%1,%2,%3}, {%4,%5,%6,%7}, {%8,%9}, {%0,%1,%2,%3};\n"
                        : "+f"(acc[mt][nt][0]), "+f"(acc[mt][nt][1]),
                          "+f"(acc[mt][nt][2]), "+f"(acc[mt][nt][3])
                        : "r"(a[mt][0]), "r"(a[mt][1]), "r"(a[mt][2]), "r"(a[mt][3]),
                          "r"(bb[0]), "r"(bb[1]));
                }
        }
        // trailing sync only needed before restaging this buffer
        if (it + 2 < T) {
            __syncthreads();
            stage(it + 2, cur);
        }
    }

    // epilogue: scatter rows to token slots
#pragma unroll
    for (int mt = 0; mt < 2; mt++) {
#pragma unroll
        for (int half = 0; half < 2; half++) {
            const int lrow = warp_m + mt * 16 + g + half * 8;
            if (row0 + lrow < count) {
                const int t = s_tok[lrow];
                float* orow = out + (long long)t * EMB_D + col0 + warp_n;
#pragma unroll
                for (int nt = 0; nt < 8; nt++) {
                    float2 v;
                    v.x = acc[mt][nt][half * 2 + 0];
                    v.y = acc[mt][nt][half * 2 + 1];
                    *(float2*)&orow[nt * 8 + tig * 2] = v;
                }
            }
        }
    }
}

extern "C" void kernel_launch(void* const* d_in, const int* in_sizes, int n_in,
                              void* d_out, int out_size) {
    const void* x = nullptr;
    Params p;
    p.d[0] = 1024; p.d[1] = 512; p.d[2] = 256; p.d[3] = 128;

    for (int i = 0; i < n_in; i++) {
        switch (in_sizes[i]) {
            case 32768:    x        = d_in[i]; break;
            case 307200:   p.emb[0] = (const float*)d_in[i]; break;
            case 1048576:  p.W[0]   = (const float*)d_in[i]; break;
            case 1382400:  p.emb[1] = (const float*)d_in[i]; break;
            case 524288:   p.W[1]   = (const float*)d_in[i]; break;
            case 6912000:  p.emb[2] = (const float*)d_in[i]; break;
            case 262144:   p.W[2]   = (const float*)d_in[i]; break;
            case 30429952: p.emb[3] = (const float*)d_in[i]; break;
            case 131072:   p.W[3]   = (const float*)d_in[i]; break;
            default: break;
        }
    }

    float* out = (float*)d_out;

    void* counts_ptr = nullptr;
    cudaGetSymbolAddress(&counts_ptr, g_counts);
    cudaMemsetAsync(counts_ptr, 0, 4 * sizeof(int));

    classify_wconv_kernel<<<640, 256>>>(x, p);
    gather_kernel<<<dim3(512, 4), 256>>>(p);

    cudaFuncSetAttribute(bucket_gemm_f16_kernel,
                         cudaFuncAttributeMaxDynamicSharedMemorySize, SMEM_BYTES);
    dim3 grid(EMB_D / BN, MAX_TILES - 4);
    bucket_gemm_f16_kernel<<<grid, 256, SMEM_BYTES>>>(out);
}

// round 17
// speedup vs baseline: 1.0309x; 1.0309x over previous
#include <cuda_runtime.h>
#include <cuda_fp16.h>
#include <stdint.h>

#define N_TOK 32768
#define EMB_D 1024
#define BM 128
#define BN 128
#define BKH 64          // k-tile in halves (128 bytes)

#define A_TILE_B (BM * BKH * 2)       // 16KB
#define B_TILE_B (BKH * BN * 2)       // 16KB
#define SMEM_BYTES (2 * A_TILE_B + 2 * B_TILE_B + BM * 4)
#define MAX_TY 260

// device scratch (no runtime allocation allowed)
__device__ __align__(16) int g_counts[4];
__device__ int g_list[4 * N_TOK];
__device__ __half g_Wh[1966080];            // all W tables, fp16, K-major
__device__ __half g_Ah[62914560];           // packed gathered A rows, fp16

__constant__ long long c_abase[4] = {0, 33554432, 50331648, 58720256};
__constant__ long long c_wbase[4] = {0, 1048576, 1572864, 1835008};
__constant__ int c_d[4] = {1024, 512, 256, 128};

struct Params {
    const float* emb[4];
    const float* W[4];
    int d[4];
};

__device__ __forceinline__ uint32_t pack_h2(float a, float b) {
    __half2 h = __floats2half2_rn(a, b);
    return *(uint32_t*)&h;
}

__device__ __forceinline__ void cp16(uint32_t sdst, const __half* gsrc, bool full) {
    int sz = full ? 16 : 0;
    asm volatile("cp.async.cg.shared.global [%0], [%1], 16, %2;\n"
                 :: "r"(sdst), "l"(gsrc), "r"(sz));
}

__device__ __forceinline__ void ldsm_x4(uint32_t* r, uint32_t addr) {
    asm volatile("ldmatrix.sync.aligned.m8n8.x4.shared.b16 {%0,%1,%2,%3}, [%4];"
                 : "=r"(r[0]), "=r"(r[1]), "=r"(r[2]), "=r"(r[3]) : "r"(addr));
}
__device__ __forceinline__ void ldsm_x4_t(uint32_t* r, uint32_t addr) {
    asm volatile("ldmatrix.sync.aligned.m8n8.x4.trans.shared.b16 {%0,%1,%2,%3}, [%4];"
                 : "=r"(r[0]), "=r"(r[1]), "=r"(r[2]), "=r"(r[3]) : "r"(addr));
}

// ---------------- stage 1: classify+gather (blocks 0-255) + W convert (256-767) ----------------
// A classify block learns the final packed position of each of its tokens from
// its block-level atomics, so it gathers/converts those rows itself — no second
// launch, no g_rows round-trip. Gather uses the proven flat chunk-per-thread shape.

__global__ __launch_bounds__(256)
void stage1_kernel(const void* __restrict__ xraw, Params p) {
    const int blk = blockIdx.x;
    const int tid = threadIdx.x;

    if (blk >= 256) {
        // W conversion (independent): 245,760 8-float chunks over 512 blocks
        const int t0 = (blk - 256) * 256 + tid;
        for (int idx = t0; idx < 1966080 / 8; idx += 512 * 256) {
            long long i = (long long)idx * 8;
            int b = (i >= c_wbase[3]) ? 3 : (i >= c_wbase[2]) ? 2 :
                    (i >= c_wbase[1]) ? 1 : 0;
            const float* src = p.W[b] + (i - c_wbase[b]);
            float4 v0 = *(const float4*)(src);
            float4 v1 = *(const float4*)(src + 4);
            uint4 u = make_uint4(pack_h2(v0.x, v0.y), pack_h2(v0.z, v0.w),
                                 pack_h2(v1.x, v1.y), pack_h2(v1.z, v1.w));
            *(uint4*)&g_Wh[i] = u;
        }
        return;
    }

    __shared__ int s_cnt[4];
    __shared__ int s_base[4];
    __shared__ int s_seg[5];
    __shared__ int s_warp[4][4];
    __shared__ int s_row[128];   // emb row index, segmented by bucket
    __shared__ int s_pos[128];   // global packed position, segmented by bucket

    const int lane = tid & 31;
    const int wid = tid >> 5;
    if (tid < 4) s_cnt[tid] = 0;
    __syncthreads();

    int b = 0, rank = 0, vrow = 0;
    if (tid < 128) {
        // dtype-robust id load (JAX default x64-off => int32)
        const unsigned int* xw = (const unsigned int*)xraw;
        unsigned int probe = xw[2 * (tid & 15) + 1];
        bool is64 = __all_sync(0xFFFFFFFFu, probe == 0u);

        const int i = blk * 128 + tid;
        int v;
        if (is64) v = (int)((const long long*)xraw)[i];
        else      v = ((const int*)xraw)[i];

        int lo;
        if (v >= 30000)     { b = 3; lo = 30000; }
        else if (v >= 3000) { b = 2; lo = 3000; }
        else if (v >= 300)  { b = 1; lo = 300; }
        else                { b = 0; lo = 0; }
        vrow = v - lo;

        const uint32_t m0 = __ballot_sync(0xFFFFFFFFu, b == 0);
        const uint32_t m1 = __ballot_sync(0xFFFFFFFFu, b == 1);
        const uint32_t m2 = __ballot_sync(0xFFFFFFFFu, b == 2);
        const uint32_t m3 = __ballot_sync(0xFFFFFFFFu, b == 3);
        const uint32_t mb = (b == 0) ? m0 : (b == 1) ? m1 : (b == 2) ? m2 : m3;
        rank = __popc(mb & ((1u << lane) - 1));

        if (lane < 4) {
            uint32_t mk = (lane == 0) ? m0 : (lane == 1) ? m1 :
                          (lane == 2) ? m2 : m3;
            s_warp[wid][lane] = atomicAdd(&s_cnt[lane], __popc(mk));
        }
    }
    __syncthreads();
    if (tid < 4) s_base[tid] = atomicAdd(&g_counts[tid], s_cnt[tid]);
    if (tid == 0) {
        s_seg[0] = 0;
        s_seg[1] = s_cnt[0];
        s_seg[2] = s_cnt[0] + s_cnt[1];
        s_seg[3] = s_cnt[0] + s_cnt[1] + s_cnt[2];
        s_seg[4] = s_cnt[0] + s_cnt[1] + s_cnt[2] + s_cnt[3];
    }
    __syncthreads();

    if (tid < 128) {
        const int local = s_warp[wid][b] + rank;
        const int pos = s_base[b] + local;
        g_list[b * N_TOK + pos] = blk * 128 + tid;
        const int ord = s_seg[b] + local;
        s_row[ord] = vrow;
        s_pos[ord] = pos;
    }
    __syncthreads();

    // gather this block's tokens: flat chunk-per-thread per bucket segment
#pragma unroll 1
    for (int bb = 0; bb < 4; bb++) {
        const int seg0 = s_seg[bb];
        const int nb = s_seg[bb + 1] - seg0;
        if (nb == 0) continue;
        const int d = p.d[bb];
        const int lg = (bb == 0) ? 7 : (bb == 1) ? 6 : (bb == 2) ? 5 : 4;
        const int cmask = (1 << lg) - 1;
        const int total = nb << lg;
        const float* __restrict__ emb = p.emb[bb];
        __half* __restrict__ dst0 = g_Ah + c_abase[bb];
        for (int idx = tid; idx < total; idx += 256) {
            const int j = seg0 + (idx >> lg);
            const int c = (idx & cmask) * 8;
            const float* src = emb + (long long)s_row[j] * d + c;
            float4 v0 = *(const float4*)(src);
            float4 v1 = *(const float4*)(src + 4);
            uint4 u = make_uint4(pack_h2(v0.x, v0.y), pack_h2(v0.z, v0.w),
                                 pack_h2(v1.x, v1.y), pack_h2(v1.z, v1.w));
            *(uint4*)&dst0[(long long)s_pos[j] * d + c] = u;
        }
    }
}

// ---------------- GEMM (R15 pipeline; tile mapping from g_counts prefix) ----------------

__global__ __launch_bounds__(256, 2)
void bucket_gemm_f16_kernel(float* __restrict__ out) {
    const int ty = blockIdx.y;
    const int4 cc = *(const int4*)g_counts;
    const int n0 = (cc.x + BM - 1) >> 7;
    const int n1 = (cc.y + BM - 1) >> 7;
    const int n2 = (cc.z + BM - 1) >> 7;
    const int n3 = (cc.w + BM - 1) >> 7;

    int b, m, count;
    if (ty < n0)                 { b = 0; m = ty;                count = cc.x; }
    else if (ty < n0 + n1)       { b = 1; m = ty - n0;           count = cc.y; }
    else if (ty < n0 + n1 + n2)  { b = 2; m = ty - n0 - n1;      count = cc.z; }
    else if (ty < n0 + n1 + n2 + n3) { b = 3; m = ty - n0 - n1 - n2; count = cc.w; }
    else return;

    const int row0 = m * BM;
    const int d = c_d[b];
    const int col0 = blockIdx.x * BN;
    const __half* __restrict__ Ab = g_Ah + c_abase[b];
    const __half* __restrict__ Wb = g_Wh + c_wbase[b];

    extern __shared__ __align__(16) char smem[];
    char* A_sm = smem;
    char* B_sm = smem + 2 * A_TILE_B;
    int* s_tok = (int*)(smem + 2 * A_TILE_B + 2 * B_TILE_B);

    const uint32_t sA = (uint32_t)__cvta_generic_to_shared(A_sm);
    const uint32_t sB = (uint32_t)__cvta_generic_to_shared(B_sm);

    const int tid = threadIdx.x;
    const int lane = tid & 31;
    const int wid = tid >> 5;
    const int g = lane >> 2;
    const int tig = lane & 3;
    const int warp_m = (wid & 3) * 32;
    const int warp_n = (wid >> 2) * 64;

    if (tid < BM) {
        s_tok[tid] = (row0 + tid < count) ? g_list[b * N_TOK + row0 + tid] : 0;
    }

    const int a_r = tid >> 1;
    const int a_c0 = (tid & 1) * 4;
    const bool a_ok = (row0 + a_r) < count;
    const __half* a_src = Ab + (long long)(row0 + a_r) * d;
    const int b_r = tid >> 2;
    const int b_c0 = (tid & 3) * 4;
    const __half* b_src = Wb + (long long)b_r * EMB_D + col0;

    auto stage = [&](int it, int buf) {
        uint32_t adst = sA + buf * A_TILE_B + a_r * 128;
        const __half* as = a_src + it * BKH;
#pragma unroll
        for (int j = 0; j < 4; j++) {
            int c = a_c0 + j;
            cp16(adst + ((c ^ (a_r & 7)) << 4), as + c * 8, a_ok);
        }
        uint32_t bdst = sB + buf * B_TILE_B + b_r * 256;
        const __half* bs = b_src + (long long)(it * BKH) * EMB_D;
#pragma unroll
        for (int j = 0; j < 4; j++) {
            int c = b_c0 + j;
            int cs = (c & 8) | ((c & 7) ^ (b_r & 7));
            cp16(bdst + (cs << 4), bs + c * 8, true);
        }
        asm volatile("cp.async.commit_group;\n" ::: "memory");
    };

    float acc[2][8][4];
#pragma unroll
    for (int mt = 0; mt < 2; mt++)
#pragma unroll
        for (int nt = 0; nt < 8; nt++)
#pragma unroll
            for (int c = 0; c < 4; c++) acc[mt][nt][c] = 0.0f;

    const int T = d / BKH;   // 16/8/4/2
    stage(0, 0);
    if (T > 1) stage(1, 1);

    for (int it = 0; it < T; it++) {
        const int cur = it & 1;
        if (it + 1 < T)
            asm volatile("cp.async.wait_group 1;\n" ::: "memory");
        else
            asm volatile("cp.async.wait_group 0;\n" ::: "memory");
        __syncthreads();

        const uint32_t aBase = sA + cur * A_TILE_B;
        const uint32_t bBase = sB + cur * B_TILE_B;
#pragma unroll
        for (int ks = 0; ks < 4; ks++) {
            const int kk = ks * 16;
            uint32_t a[2][4];
#pragma unroll
            for (int mt = 0; mt < 2; mt++) {
                int r = warp_m + mt * 16 + (lane & 15);
                int chunk = (kk >> 3) + (lane >> 4);
                ldsm_x4(a[mt], aBase + r * 128 + ((chunk ^ (r & 7)) << 4));
            }
            uint32_t bf[4][4];
#pragma unroll
            for (int pr = 0; pr < 4; pr++) {
                int kr = kk + (lane & 15);
                int chunk = (warp_n >> 3) + pr * 2 + (lane >> 4);
                int cs = (chunk & 8) | ((chunk & 7) ^ (kr & 7));
                ldsm_x4_t(bf[pr], bBase + kr * 256 + (cs << 4));
            }
#pragma unroll
            for (int mt = 0; mt < 2; mt++)
#pragma unroll
                for (int nt = 0; nt < 8; nt++) {
                    const uint32_t* bb = &bf[nt >> 1][(nt & 1) * 2];
                    asm volatile(
                        "mma.sync.aligned.m16n8k16.row.col.f32.f16.f16.f32 "
                        "{%0,%1,%2,%3}, {%4,%5,%6,%7}, {%8,%9}, {%0,%1,%2,%3};\n"
                        : "+f"(acc[mt][nt][0]), "+f"(acc[mt][nt][1]),
                          "+f"(acc[mt][nt][2]), "+f"(acc[mt][nt][3])
                        : "r"(a[mt][0]), "r"(a[mt][1]), "r"(a[mt][2]), "r"(a[mt][3]),
                          "r"(bb[0]), "r"(bb[1]));
                }
        }
        // trailing sync only needed before restaging this buffer
        if (it + 2 < T) {
            __syncthreads();
            stage(it + 2, cur);
        }
    }

    // epilogue: scatter rows to token slots
#pragma unroll
    for (int mt = 0; mt < 2; mt++) {
#pragma unroll
        for (int half = 0; half < 2; half++) {
            const int lrow = warp_m + mt * 16 + g + half * 8;
            if (row0 + lrow < count) {
                const int t = s_tok[lrow];
                float* orow = out + (long long)t * EMB_D + col0 + warp_n;
#pragma unroll
                for (int nt = 0; nt < 8; nt++) {
                    float2 v;
                    v.x = acc[mt][nt][half * 2 + 0];
                    v.y = acc[mt][nt][half * 2 + 1];
                    *(float2*)&orow[nt * 8 + tig * 2] = v;
                }
            }
        }
    }
}

extern "C" void kernel_launch(void* const* d_in, const int* in_sizes, int n_in,
                              void* d_out, int out_size) {
    const void* x = nullptr;
    Params p;
    p.d[0] = 1024; p.d[1] = 512; p.d[2] = 256; p.d[3] = 128;

    for (int i = 0; i < n_in; i++) {
        switch (in_sizes[i]) {
            case 32768:    x        = d_in[i]; break;
            case 307200:   p.emb[0] = (const float*)d_in[i]; break;
            case 1048576:  p.W[0]   = (const float*)d_in[i]; break;
            case 1382400:  p.emb[1] = (const float*)d_in[i]; break;
            case 524288:   p.W[1]   = (const float*)d_in[i]; break;
            case 6912000:  p.emb[2] = (const float*)d_in[i]; break;
            case 262144:   p.W[2]   = (const float*)d_in[i]; break;
            case 30429952: p.emb[3] = (const float*)d_in[i]; break;
            case 131072:   p.W[3]   = (const float*)d_in[i]; break;
            default: break;
        }
    }

    float* out = (float*)d_out;

    void* counts_ptr = nullptr;
    cudaGetSymbolAddress(&counts_ptr, g_counts);
    cudaMemsetAsync(counts_ptr, 0, 4 * sizeof(int));

    stage1_kernel<<<768, 256>>>(x, p);

    cudaFuncSetAttribute(bucket_gemm_f16_kernel,
                         cudaFuncAttributeMaxDynamicSharedMemorySize, SMEM_BYTES);
    dim3 grid(EMB_D / BN, MAX_TY);
    bucket_gemm_f16_kernel<<<grid, 256, SMEM_BYTES>>>(out);
}